// round 16
// baseline (speedup 1.0000x reference)
#include <cuda_runtime.h>
#include <cuda.h>
#include <cuda_fp16.h>
#include <cstdint>
#include <math.h>

#define BATCH 4
#define SEQ   2048
#define DMODEL 1024

// ---------------- device scratch ----------------
__device__ __align__(128) __half g_xh[8388608];                // x fp16 [8192][1024]
__device__ __align__(128) __half g_wqt[1048576];
__device__ __align__(128) __half g_wkt[1048576];
__device__ __align__(128) __half g_wvt[1048576];
__device__ __align__(128) __half g_q[8388608];
__device__ __align__(128) __half g_k[8388608];
__device__ __align__(128) __half g_vt[8388608];                // V^T [4096][2048]
__device__ __align__(128) __half g_p[16777216];                // exp(scores) fp16
__device__ __align__(128) float  g_part[262144];               // row partial sums [8192][32]

// ---------------- helpers ----------------
__device__ __forceinline__ uint32_t smem_u32(const void* p) {
    uint32_t a;
    asm("{ .reg .u64 t; cvta.to.shared.u64 t, %1; cvt.u32.u64 %0, t; }" : "=r"(a) : "l"(p));
    return a;
}
__device__ __forceinline__ void ldsm4(uint32_t* r, uint32_t a) {
    asm volatile("ldmatrix.sync.aligned.m8n8.x4.shared.b16 {%0,%1,%2,%3}, [%4];"
        : "=r"(r[0]), "=r"(r[1]), "=r"(r[2]), "=r"(r[3]) : "r"(a));
}
__device__ __forceinline__ void mma_f16(float* c, const uint32_t* a, const uint32_t* b) {
    asm volatile("mma.sync.aligned.m16n8k16.row.col.f32.f16.f16.f32 "
        "{%0,%1,%2,%3}, {%4,%5,%6,%7}, {%8,%9}, {%0,%1,%2,%3};"
        : "+f"(c[0]), "+f"(c[1]), "+f"(c[2]), "+f"(c[3])
        : "r"(a[0]), "r"(a[1]), "r"(a[2]), "r"(a[3]), "r"(b[0]), "r"(b[1]));
}
__device__ __forceinline__ void stg2_cs(float* p, float x, float y) {
    asm volatile("st.global.cs.v2.f32 [%0], {%1, %2};" :: "l"(p), "f"(x), "f"(y) : "memory");
}
#define MBAR_INIT(a, c)   asm volatile("mbarrier.init.shared.b64 [%0], %1;" :: "r"(a), "r"(c) : "memory")
#define MBAR_EXPECT(a, b) asm volatile("mbarrier.arrive.expect_tx.shared.b64 _, [%0], %1;" :: "r"(a), "r"(b) : "memory")
#define MBAR_ARRIVE(a)    asm volatile("mbarrier.arrive.shared.b64 _, [%0];" :: "r"(a) : "memory")
#define FENCE_ASYNC()     asm volatile("fence.proxy.async.shared::cta;" ::: "memory")

__device__ __forceinline__ void mbar_wait(uint32_t mbar, uint32_t parity) {
    uint32_t done;
    asm volatile("{\n\t.reg .pred p;\n\t"
        "mbarrier.try_wait.parity.acquire.cta.shared::cta.b64 p, [%1], %2;\n\t"
        "selp.b32 %0, 1, 0, p;\n\t}"
        : "=r"(done) : "r"(mbar), "r"(parity) : "memory");
    while (!done) {
        asm volatile("{\n\t.reg .pred p;\n\t"
            "mbarrier.try_wait.parity.acquire.cta.shared::cta.b64 p, [%1], %2, 0x989680;\n\t"
            "selp.b32 %0, 1, 0, p;\n\t}"
            : "=r"(done) : "r"(mbar), "r"(parity) : "memory");
    }
}
__device__ __forceinline__ void tma2d(uint32_t dst, const CUtensorMap* tm, int x, int y, uint32_t mbar) {
    asm volatile("cp.async.bulk.tensor.2d.shared::cta.global.tile.mbarrier::complete_tx::bytes "
        "[%0], [%1, {%2, %3}], [%4];"
        :: "r"(dst), "l"(tm), "r"(x), "r"(y), "r"(mbar) : "memory");
}

// ---------------- prep kernels ----------------
__global__ __launch_bounds__(256) void cvt_kernel(const float4* __restrict__ X,
                                                  uint2* __restrict__ Y, int n4) {
    int i = blockIdx.x * 256 + threadIdx.x;
    if (i >= n4) return;
    float4 v = X[i];
    __half2 h0 = __floats2half2_rn(v.x, v.y);
    __half2 h1 = __floats2half2_rn(v.z, v.w);
    uint2 u;
    u.x = *reinterpret_cast<uint32_t*>(&h0);
    u.y = *reinterpret_cast<uint32_t*>(&h1);
    Y[i] = u;
}

__global__ __launch_bounds__(256) void wtrans3_kernel(
    const float* __restrict__ Wq, const float* __restrict__ Wk, const float* __restrict__ Wv,
    __half* __restrict__ Tq, __half* __restrict__ Tk, __half* __restrict__ Tv)
{
    const float* W = (blockIdx.z == 0) ? Wq : (blockIdx.z == 1) ? Wk : Wv;
    __half* T = (blockIdx.z == 0) ? Tq : (blockIdx.z == 1) ? Tk : Tv;

    __shared__ float t[32][33];
    int k0 = blockIdx.y * 32, n0 = blockIdx.x * 32;
    int tx = threadIdx.x & 31, ty = threadIdx.x >> 5;
    #pragma unroll
    for (int i = 0; i < 4; i++) {
        int k = ty + i * 8;
        t[k][tx] = W[(long long)(k0 + k) * DMODEL + n0 + tx];
    }
    __syncthreads();
    #pragma unroll
    for (int i = 0; i < 4; i++) {
        int n = ty + i * 8;
        T[(long long)(n0 + n) * DMODEL + k0 + tx] = __float2half_rn(t[tx][n]);
    }
}

// ---------------- shared GEMM plumbing ----------------
#define KC 64
#define TILE_B 16384                  // 128 rows x 128 B
#define STAGE_B (2 * TILE_B)          // A + B
#define NSTAGE 3
#define DSMEM (1024 + NSTAGE * STAGE_B + 768)

#define GEMM_MAINLOOP(tmAp, tmBp, mrow0, nrow0)                                           \
    if (tid == 0) {                                                                       \
        _Pragma("unroll")                                                                 \
        for (int s = 0; s < NSTAGE; s++) {                                                \
            MBAR_INIT(ctrl + s * 16, 1);                                                  \
            MBAR_INIT(ctrl + s * 16 + 8, 8);                                              \
        }                                                                                 \
        FENCE_ASYNC();                                                                    \
    }                                                                                     \
    __syncthreads();                                                                      \
    if (tid == 0) {                                                                       \
        _Pragma("unroll")                                                                 \
        for (int s = 0; s < NSTAGE; s++) {                                                \
            if (s < CH) {                                                                 \
                MBAR_EXPECT(ctrl + s * 16, 2 * TILE_B);                                   \
                tma2d(tiles + s * STAGE_B,          tmAp, s * KC, (mrow0), ctrl + s * 16);\
                tma2d(tiles + s * STAGE_B + TILE_B, tmBp, s * KC, (nrow0), ctrl + s * 16);\
            }                                                                             \
        }                                                                                 \
    }                                                                                     \
    GEMM_PROLOGUE_HOOK                                                                    \
    {                                                                                     \
        int stage = 0, phase = 0;                                                         \
        for (int c = 0; c < CH; c++) {                                                    \
            mbar_wait(ctrl + stage * 16, phase);                                          \
            const uint32_t stA = tiles + stage * STAGE_B;                                 \
            const uint32_t stB = stA + TILE_B;                                            \
            _Pragma("unroll")                                                             \
            for (int ks = 0; ks < 4; ks++) {                                              \
                const uint32_t kb = (qc + ks * 32) ^ xc;                                  \
                uint32_t a[2][4];                                                         \
                ldsm4(a[0], stA + aoff[0] + kb);                                          \
                ldsm4(a[1], stA + aoff[1] + kb);                                          \
                uint32_t bb[8][2];                                                        \
                _Pragma("unroll")                                                         \
                for (int nt2 = 0; nt2 < 4; nt2++) {                                       \
                    uint32_t r[4];                                                        \
                    ldsm4(r, stB + boff[nt2] + kb);                                       \
                    bb[nt2 * 2 + 0][0] = r[0]; bb[nt2 * 2 + 0][1] = r[2];                 \
                    bb[nt2 * 2 + 1][0] = r[1]; bb[nt2 * 2 + 1][1] = r[3];                 \
                }                                                                         \
                if (ks == 3 && lane == 0) MBAR_ARRIVE(ctrl + stage * 16 + 8);             \
                _Pragma("unroll")                                                         \
                for (int nt = 0; nt < 8; nt++) {                                          \
                    mma_f16(acc[0][nt], a[0], bb[nt]);                                    \
                    mma_f16(acc[1][nt], a[1], bb[nt]);                                    \
                }                                                                         \
            }                                                                             \
            if (tid == 0 && c + NSTAGE < CH) {                                            \
                mbar_wait(ctrl + stage * 16 + 8, phase);                                  \
                const int cn = c + NSTAGE;                                                \
                MBAR_EXPECT(ctrl + stage * 16, 2 * TILE_B);                               \
                tma2d(tiles + stage * STAGE_B,          tmAp, cn * KC, (mrow0), ctrl + stage * 16); \
                tma2d(tiles + stage * STAGE_B + TILE_B, tmBp, cn * KC, (nrow0), ctrl + stage * 16); \
            }                                                                             \
            if (++stage == NSTAGE) { stage = 0; phase ^= 1; }                             \
        }                                                                                 \
    }                                                                                     \
    __syncthreads();

#define FRAG_ADDR_SETUP()                                                \
    const uint32_t xc = (lane & 7) << 4;                                 \
    const uint32_t qc = (lane >> 4) << 4;                                \
    uint32_t aoff[2], boff[4];                                           \
    _Pragma("unroll")                                                    \
    for (int mt = 0; mt < 2; mt++)                                       \
        aoff[mt] = (wm * 32 + mt * 16 + (lane & 15)) * 128;              \
    _Pragma("unroll")                                                    \
    for (int nt2 = 0; nt2 < 4; nt2++)                                    \
        boff[nt2] = (wn * 64 + nt2 * 16 + (lane & 15)) * 128;

// ---------------- merged QKV projection (z selects q/k/v) ----------------
#define GEMM_PROLOGUE_HOOK
__global__ __launch_bounds__(256, 2)
void proj_qkv(const __grid_constant__ CUtensorMap tmX,
              const __grid_constant__ CUtensorMap tmWq,
              const __grid_constant__ CUtensorMap tmWk,
              const __grid_constant__ CUtensorMap tmWv,
              const float* __restrict__ bq, const float* __restrict__ bk, const float* __restrict__ bv,
              __half* __restrict__ Q, __half* __restrict__ Kmat, __half* __restrict__ VT)
{
    extern __shared__ char smem[];
    const uint32_t sbase = smem_u32(smem);
    const uint32_t tiles = (sbase + 1023) & ~1023u;
    const uint32_t ctrl  = tiles + NSTAGE * STAGE_B;

    const int tid = threadIdx.x, lane = tid & 31, wid = tid >> 5;
    const int wm = wid & 3, wn = wid >> 2;
    const int z = blockIdx.z;
    const int m0 = blockIdx.y * 128, n0 = blockIdx.x * 128;

    const CUtensorMap* tb = (z == 0) ? &tmWq : (z == 1) ? &tmWk : &tmWv;
    const float* bias = (z == 0) ? bq : (z == 1) ? bk : bv;

    FRAG_ADDR_SETUP()

    float acc[2][8][4] = {};
    const int CH = DMODEL / KC;

    GEMM_MAINLOOP(&tmX, tb, m0, n0)

    if (z == 2) {
        float* stg = (float*)smem;
        #pragma unroll
        for (int mt = 0; mt < 2; mt++)
            #pragma unroll
            for (int h = 0; h < 2; h++) {
                int m = wm * 32 + mt * 16 + (lane >> 2) + h * 8;
                #pragma unroll
                for (int nt = 0; nt < 8; nt++) {
                    int n = wn * 64 + nt * 8 + ((lane & 3) << 1);
                    stg[m * 133 + n]     = acc[mt][nt][h * 2 + 0] + __ldg(bias + n0 + n);
                    stg[m * 133 + n + 1] = acc[mt][nt][h * 2 + 1] + __ldg(bias + n0 + n + 1);
                }
            }
        __syncthreads();
        #pragma unroll 4
        for (int i = 0; i < 64; i++) {
            int linear = i * 256 + tid;
            int n = linear >> 7, m = linear & 127;
            float v = stg[m * 133 + n];
            int gm = m0 + m;
            long long idx = ((long long)(gm >> 11) * DMODEL + (n0 + n)) * SEQ + (gm & (SEQ - 1));
            VT[idx] = __float2half_rn(v);
        }
    } else {
        __half* C = (z == 0) ? Q : Kmat;
        #pragma unroll
        for (int mt = 0; mt < 2; mt++)
            #pragma unroll
            for (int h = 0; h < 2; h++) {
                int m = m0 + wm * 32 + mt * 16 + (lane >> 2) + h * 8;
                #pragma unroll
                for (int nt = 0; nt < 8; nt++) {
                    int n = n0 + wn * 64 + nt * 8 + ((lane & 3) << 1);
                    float v0 = acc[mt][nt][h * 2 + 0] + __ldg(bias + n);
                    float v1 = acc[mt][nt][h * 2 + 1] + __ldg(bias + n + 1);
                    __half2 hv = __floats2half2_rn(v0, v1);
                    *(__half2*)(C + (long long)m * DMODEL + n) = hv;
                }
            }
    }
}
#undef GEMM_PROLOGUE_HOOK

// ---------------- scores GEMM (per-batch): P16 = fp16(exp(acc/32)) + partials ----------------
#define GEMM_PROLOGUE_HOOK
__global__ __launch_bounds__(256, 2)
void gemm_scores(const __grid_constant__ CUtensorMap tmQ,
                 const __grid_constant__ CUtensorMap tmK,
                 __half* __restrict__ P16, float* __restrict__ partials,
                 float scale, int zofs)
{
    extern __shared__ char smem[];
    const uint32_t sbase = smem_u32(smem);
    const uint32_t tiles = (sbase + 1023) & ~1023u;
    const uint32_t ctrl  = tiles + NSTAGE * STAGE_B;

    const int tid = threadIdx.x, lane = tid & 31, wid = tid >> 5;
    const int wm = wid & 3, wn = wid >> 2;
    const int z = zofs;
    const int m0 = blockIdx.y * 128, n0 = blockIdx.x * 128;
    const int mrow0 = m0 + z * SEQ;
    const int nrow0 = n0 + z * SEQ;

    FRAG_ADDR_SETUP()

    float acc[2][8][4] = {};
    const int CH = DMODEL / KC;

    GEMM_MAINLOOP(&tmQ, &tmK, mrow0, nrow0)

    __half* Pz = P16 + (long long)z * SEQ * SEQ;
    #pragma unroll
    for (int mt = 0; mt < 2; mt++)
        #pragma unroll
        for (int h = 0; h < 2; h++) {
            int m = m0 + wm * 32 + mt * 16 + (lane >> 2) + h * 8;
            float rsum = 0.0f;
            #pragma unroll
            for (int nt = 0; nt < 8; nt++) {
                int n = n0 + wn * 64 + nt * 8 + ((lane & 3) << 1);
                float e0 = __expf(acc[mt][nt][h * 2 + 0] * scale);
                float e1 = __expf(acc[mt][nt][h * 2 + 1] * scale);
                rsum += e0 + e1;
                __half2 hv = __floats2half2_rn(e0, e1);
                *(__half2*)(Pz + (long long)m * SEQ + n) = hv;
            }
            rsum += __shfl_xor_sync(0xffffffffu, rsum, 1);
            rsum += __shfl_xor_sync(0xffffffffu, rsum, 2);
            if ((lane & 3) == 0)
                partials[((long long)z * SEQ + m) * 32 + blockIdx.x * 2 + wn] = rsum;
        }
}
#undef GEMM_PROLOGUE_HOOK

// ---------------- PV GEMM (per-batch): out = (P V) / rowsum; rowinv fused in prologue ----------------
#define GEMM_PROLOGUE_HOOK                                                 \
    {                                                                      \
        float* sinv = (float*)(smem + (ctrl - sbase) + 128);               \
        if (tid < 128) {                                                   \
            const float4* pp = (const float4*)(partials +                  \
                ((long long)z * SEQ + m0 + tid) * 32);                     \
            float ssum = 0.0f;                                             \
            _Pragma("unroll")                                              \
            for (int i = 0; i < 8; i++) {                                  \
                float4 v = pp[i];                                          \
                ssum += (v.x + v.y) + (v.z + v.w);                         \
            }                                                              \
            sinv[tid] = 1.0f / ssum;                                       \
        }                                                                  \
    }
__global__ __launch_bounds__(256, 2)
void gemm_pv(const __grid_constant__ CUtensorMap tmP,
             const __grid_constant__ CUtensorMap tmVT,
             const float* __restrict__ partials, float* __restrict__ C,
             int zofs)
{
    extern __shared__ char smem[];
    const uint32_t sbase = smem_u32(smem);
    const uint32_t tiles = (sbase + 1023) & ~1023u;
    const uint32_t ctrl  = tiles + NSTAGE * STAGE_B;

    const int tid = threadIdx.x, lane = tid & 31, wid = tid >> 5;
    const int wm = wid & 3, wn = wid >> 2;
    const int z = zofs;
    const int m0 = blockIdx.y * 128, n0 = blockIdx.x * 128;
    const int mrow0 = m0 + z * SEQ;
    const int nrow0 = n0 + z * DMODEL;

    FRAG_ADDR_SETUP()

    float acc[2][8][4] = {};
    const int CH = SEQ / KC;

    GEMM_MAINLOOP(&tmP, &tmVT, mrow0, nrow0)

    const float* sinv = (const float*)(smem + (ctrl - sbase) + 128);
    float* Cz = C + (long long)z * SEQ * DMODEL;
    #pragma unroll
    for (int mt = 0; mt < 2; mt++)
        #pragma unroll
        for (int h = 0; h < 2; h++) {
            int mloc = wm * 32 + mt * 16 + (lane >> 2) + h * 8;
            int m = m0 + mloc;
            float iv = sinv[mloc];
            #pragma unroll
            for (int nt = 0; nt < 8; nt++) {
                int n = n0 + wn * 64 + nt * 8 + ((lane & 3) << 1);
                stg2_cs(Cz + (long long)m * DMODEL + n,
                        acc[mt][nt][h * 2 + 0] * iv,
                        acc[mt][nt][h * 2 + 1] * iv);
            }
        }
}
#undef GEMM_PROLOGUE_HOOK

// ---------------- host: tensormap encode via driver entry point ----------------
typedef CUresult (*EncodeFn)(CUtensorMap*, CUtensorMapDataType, cuuint32_t, void*,
                             const cuuint64_t*, const cuuint64_t*, const cuuint32_t*,
                             const cuuint32_t*, CUtensorMapInterleave, CUtensorMapSwizzle,
                             CUtensorMapL2promotion, CUtensorMapFloatOOBfill);

static void make2d_h(EncodeFn enc, CUtensorMap* m, void* p, unsigned long long rows, unsigned long long cols) {
    cuuint64_t dims[2]    = {cols, rows};
    cuuint64_t strides[1] = {cols * 2};
    cuuint32_t box[2]     = {64, 128};
    cuuint32_t es[2]      = {1, 1};
    enc(m, CU_TENSOR_MAP_DATA_TYPE_FLOAT16, 2, p, dims, strides, box, es,
        CU_TENSOR_MAP_INTERLEAVE_NONE, CU_TENSOR_MAP_SWIZZLE_128B,
        CU_TENSOR_MAP_L2_PROMOTION_L2_128B, CU_TENSOR_MAP_FLOAT_OOB_FILL_NONE);
}

// ---------------- launch ----------------
extern "C" void kernel_launch(void* const* d_in, const int* in_sizes, int n_in,
                              void* d_out, int out_size)
{
    const float* x  = (const float*)d_in[0];
    const float* Wq = (const float*)d_in[1];
    const float* bq = (const float*)d_in[2];
    const float* Wk = (const float*)d_in[3];
    const float* bk = (const float*)d_in[4];
    const float* Wv = (const float*)d_in[5];
    const float* bv = (const float*)d_in[6];
    float* out = (float*)d_out;

    void *xh, *wqt, *wkt, *wvt, *q, *k, *vt, *p, *part;
    cudaGetSymbolAddress(&xh, g_xh);
    cudaGetSymbolAddress(&wqt, g_wqt); cudaGetSymbolAddress(&wkt, g_wkt); cudaGetSymbolAddress(&wvt, g_wvt);
    cudaGetSymbolAddress(&q, g_q); cudaGetSymbolAddress(&k, g_k);
    cudaGetSymbolAddress(&vt, g_vt);
    cudaGetSymbolAddress(&p, g_p);
    cudaGetSymbolAddress(&part, g_part);

    EncodeFn enc = nullptr;
    {
        void* fp = nullptr;
        cudaDriverEntryPointQueryResult qr;
        cudaGetDriverEntryPointByVersion("cuTensorMapEncodeTiled", &fp, 12000,
                                         cudaEnableDefault, &qr);
        enc = (EncodeFn)fp;
    }
    CUtensorMap tm_x, tm_wq, tm_wk, tm_wv, tm_q, tm_k, tm_p, tm_vt;
    make2d_h(enc, &tm_x,  xh,  8192, 1024);
    make2d_h(enc, &tm_wq, wqt, 1024, 1024);
    make2d_h(enc, &tm_wk, wkt, 1024, 1024);
    make2d_h(enc, &tm_wv, wvt, 1024, 1024);
    make2d_h(enc, &tm_q,  q,   8192, 1024);
    make2d_h(enc, &tm_k,  k,   8192, 1024);
    make2d_h(enc, &tm_p,  p,   8192, 2048);
    make2d_h(enc, &tm_vt, vt,  4096, 2048);

    cudaFuncSetAttribute(proj_qkv,    cudaFuncAttributeMaxDynamicSharedMemorySize, DSMEM);
    cudaFuncSetAttribute(gemm_scores, cudaFuncAttributeMaxDynamicSharedMemorySize, DSMEM);
    cudaFuncSetAttribute(gemm_pv,     cudaFuncAttributeMaxDynamicSharedMemorySize, DSMEM);

    // side stream + events (lazily created host objects; per-call work unchanged)
    static cudaStream_t s2 = nullptr;
    static cudaEvent_t evFork = nullptr, evCvt = nullptr, evJoin = nullptr;
    static cudaEvent_t evS[BATCH] = {};
    if (!s2) {
        cudaStreamCreateWithFlags(&s2, cudaStreamNonBlocking);
        cudaEventCreateWithFlags(&evFork, cudaEventDisableTiming);
        cudaEventCreateWithFlags(&evCvt,  cudaEventDisableTiming);
        cudaEventCreateWithFlags(&evJoin, cudaEventDisableTiming);
        for (int i = 0; i < BATCH; i++)
            cudaEventCreateWithFlags(&evS[i], cudaEventDisableTiming);
    }

    const int MQ = BATCH * SEQ; // 8192

    // prep: x-convert on s2, weight transpose on default (independent)
    cudaEventRecord(evFork, 0);
    cudaStreamWaitEvent(s2, evFork, 0);
    cvt_kernel<<<MQ * DMODEL / 4 / 256, 256, 0, s2>>>((const float4*)x, (uint2*)xh, MQ * DMODEL / 4);
    cudaEventRecord(evCvt, s2);

    dim3 gw(DMODEL / 32, DMODEL / 32, 3);
    wtrans3_kernel<<<gw, 256>>>(Wq, Wk, Wv, (__half*)wqt, (__half*)wkt, (__half*)wvt);
    cudaStreamWaitEvent(0, evCvt, 0);

    // merged QKV projections
    dim3 gp(DMODEL / 128, MQ / 128, 3);
    proj_qkv<<<gp, 256, DSMEM>>>(tm_x, tm_wq, tm_wk, tm_wv, bq, bk, bv,
                                 (__half*)q, (__half*)k, (__half*)vt);

    // pipelined per-batch scores (default) and PV (s2)
    dim3 gs(SEQ / 128, SEQ / 128, 1);
    dim3 go(DMODEL / 128, SEQ / 128, 1);
    for (int z = 0; z < BATCH; z++) {
        gemm_scores<<<gs, 256, DSMEM>>>(tm_q, tm_k, (__half*)p, (float*)part, 0.03125f, z);
        cudaEventRecord(evS[z], 0);
        cudaStreamWaitEvent(s2, evS[z], 0);
        gemm_pv<<<go, 256, DSMEM, s2>>>(tm_p, tm_vt, (const float*)part, out, z);
    }
    cudaEventRecord(evJoin, s2);
    cudaStreamWaitEvent(0, evJoin, 0);
}

// round 17
// speedup vs baseline: 1.0936x; 1.0936x over previous
#include <cuda_runtime.h>
#include <cuda.h>
#include <cuda_fp16.h>
#include <cstdint>
#include <math.h>

#define BATCH 4
#define SEQ   2048
#define DMODEL 1024

// ---------------- device scratch ----------------
__device__ __align__(128) __half g_xh[8388608];                // x fp16 [8192][1024]
__device__ __align__(128) __half g_wqt[1048576];
__device__ __align__(128) __half g_wkt[1048576];
__device__ __align__(128) __half g_wvt[1048576];
__device__ __align__(128) __half g_q[8388608];
__device__ __align__(128) __half g_k[8388608];
__device__ __align__(128) __half g_vt[8388608];                // V^T [4096][2048]
__device__ __align__(128) __half g_p[16777216];                // exp(scores) fp16
__device__ __align__(128) float  g_part[262144];               // row partial sums [8192][32]

// ---------------- helpers ----------------
__device__ __forceinline__ uint32_t smem_u32(const void* p) {
    uint32_t a;
    asm("{ .reg .u64 t; cvta.to.shared.u64 t, %1; cvt.u32.u64 %0, t; }" : "=r"(a) : "l"(p));
    return a;
}
__device__ __forceinline__ void ldsm4(uint32_t* r, uint32_t a) {
    asm volatile("ldmatrix.sync.aligned.m8n8.x4.shared.b16 {%0,%1,%2,%3}, [%4];"
        : "=r"(r[0]), "=r"(r[1]), "=r"(r[2]), "=r"(r[3]) : "r"(a));
}
__device__ __forceinline__ void mma_f16(float* c, const uint32_t* a, const uint32_t* b) {
    asm volatile("mma.sync.aligned.m16n8k16.row.col.f32.f16.f16.f32 "
        "{%0,%1,%2,%3}, {%4,%5,%6,%7}, {%8,%9}, {%0,%1,%2,%3};"
        : "+f"(c[0]), "+f"(c[1]), "+f"(c[2]), "+f"(c[3])
        : "r"(a[0]), "r"(a[1]), "r"(a[2]), "r"(a[3]), "r"(b[0]), "r"(b[1]));
}
__device__ __forceinline__ void stg2_cs(float* p, float x, float y) {
    asm volatile("st.global.cs.v2.f32 [%0], {%1, %2};" :: "l"(p), "f"(x), "f"(y) : "memory");
}
#define MBAR_INIT(a, c)   asm volatile("mbarrier.init.shared.b64 [%0], %1;" :: "r"(a), "r"(c) : "memory")
#define MBAR_EXPECT(a, b) asm volatile("mbarrier.arrive.expect_tx.shared.b64 _, [%0], %1;" :: "r"(a), "r"(b) : "memory")
#define MBAR_ARRIVE(a)    asm volatile("mbarrier.arrive.shared.b64 _, [%0];" :: "r"(a) : "memory")
#define FENCE_ASYNC()     asm volatile("fence.proxy.async.shared::cta;" ::: "memory")

__device__ __forceinline__ void mbar_wait(uint32_t mbar, uint32_t parity) {
    uint32_t done;
    asm volatile("{\n\t.reg .pred p;\n\t"
        "mbarrier.try_wait.parity.acquire.cta.shared::cta.b64 p, [%1], %2;\n\t"
        "selp.b32 %0, 1, 0, p;\n\t}"
        : "=r"(done) : "r"(mbar), "r"(parity) : "memory");
    while (!done) {
        asm volatile("{\n\t.reg .pred p;\n\t"
            "mbarrier.try_wait.parity.acquire.cta.shared::cta.b64 p, [%1], %2, 0x989680;\n\t"
            "selp.b32 %0, 1, 0, p;\n\t}"
            : "=r"(done) : "r"(mbar), "r"(parity) : "memory");
    }
}
__device__ __forceinline__ void tma2d(uint32_t dst, const CUtensorMap* tm, int x, int y, uint32_t mbar) {
    asm volatile("cp.async.bulk.tensor.2d.shared::cta.global.tile.mbarrier::complete_tx::bytes "
        "[%0], [%1, {%2, %3}], [%4];"
        :: "r"(dst), "l"(tm), "r"(x), "r"(y), "r"(mbar) : "memory");
}

// ---------------- prep kernels ----------------
__global__ __launch_bounds__(256) void cvt_kernel(const float4* __restrict__ X,
                                                  uint2* __restrict__ Y, int n4) {
    int i = blockIdx.x * 256 + threadIdx.x;
    if (i >= n4) return;
    float4 v = X[i];
    __half2 h0 = __floats2half2_rn(v.x, v.y);
    __half2 h1 = __floats2half2_rn(v.z, v.w);
    uint2 u;
    u.x = *reinterpret_cast<uint32_t*>(&h0);
    u.y = *reinterpret_cast<uint32_t*>(&h1);
    Y[i] = u;
}

__global__ __launch_bounds__(256) void wtrans3_kernel(
    const float* __restrict__ Wq, const float* __restrict__ Wk, const float* __restrict__ Wv,
    __half* __restrict__ Tq, __half* __restrict__ Tk, __half* __restrict__ Tv)
{
    const float* W = (blockIdx.z == 0) ? Wq : (blockIdx.z == 1) ? Wk : Wv;
    __half* T = (blockIdx.z == 0) ? Tq : (blockIdx.z == 1) ? Tk : Tv;

    __shared__ float t[32][33];
    int k0 = blockIdx.y * 32, n0 = blockIdx.x * 32;
    int tx = threadIdx.x & 31, ty = threadIdx.x >> 5;
    #pragma unroll
    for (int i = 0; i < 4; i++) {
        int k = ty + i * 8;
        t[k][tx] = W[(long long)(k0 + k) * DMODEL + n0 + tx];
    }
    __syncthreads();
    #pragma unroll
    for (int i = 0; i < 4; i++) {
        int n = ty + i * 8;
        T[(long long)(n0 + n) * DMODEL + k0 + tx] = __float2half_rn(t[tx][n]);
    }
}

// ---------------- shared GEMM plumbing ----------------
#define KC 64
#define TILE_B 16384                  // 128 rows x 128 B
#define STAGE_B (2 * TILE_B)          // A + B
#define NSTAGE 3
#define DSMEM (1024 + NSTAGE * STAGE_B + 768)

#define GEMM_MAINLOOP(tmAp, tmBp, mrow0, nrow0)                                           \
    if (tid == 0) {                                                                       \
        _Pragma("unroll")                                                                 \
        for (int s = 0; s < NSTAGE; s++) {                                                \
            MBAR_INIT(ctrl + s * 16, 1);                                                  \
            MBAR_INIT(ctrl + s * 16 + 8, 8);                                              \
        }                                                                                 \
        FENCE_ASYNC();                                                                    \
    }                                                                                     \
    __syncthreads();                                                                      \
    if (tid == 0) {                                                                       \
        _Pragma("unroll")                                                                 \
        for (int s = 0; s < NSTAGE; s++) {                                                \
            if (s < CH) {                                                                 \
                MBAR_EXPECT(ctrl + s * 16, 2 * TILE_B);                                   \
                tma2d(tiles + s * STAGE_B,          tmAp, s * KC, (mrow0), ctrl + s * 16);\
                tma2d(tiles + s * STAGE_B + TILE_B, tmBp, s * KC, (nrow0), ctrl + s * 16);\
            }                                                                             \
        }                                                                                 \
    }                                                                                     \
    GEMM_PROLOGUE_HOOK                                                                    \
    {                                                                                     \
        int stage = 0, phase = 0;                                                         \
        for (int c = 0; c < CH; c++) {                                                    \
            mbar_wait(ctrl + stage * 16, phase);                                          \
            const uint32_t stA = tiles + stage * STAGE_B;                                 \
            const uint32_t stB = stA + TILE_B;                                            \
            _Pragma("unroll")                                                             \
            for (int ks = 0; ks < 4; ks++) {                                              \
                const uint32_t kb = (qc + ks * 32) ^ xc;                                  \
                uint32_t a[2][4];                                                         \
                ldsm4(a[0], stA + aoff[0] + kb);                                          \
                ldsm4(a[1], stA + aoff[1] + kb);                                          \
                uint32_t bb[8][2];                                                        \
                _Pragma("unroll")                                                         \
                for (int nt2 = 0; nt2 < 4; nt2++) {                                       \
                    uint32_t r[4];                                                        \
                    ldsm4(r, stB + boff[nt2] + kb);                                       \
                    bb[nt2 * 2 + 0][0] = r[0]; bb[nt2 * 2 + 0][1] = r[2];                 \
                    bb[nt2 * 2 + 1][0] = r[1]; bb[nt2 * 2 + 1][1] = r[3];                 \
                }                                                                         \
                if (ks == 3 && lane == 0) MBAR_ARRIVE(ctrl + stage * 16 + 8);             \
                _Pragma("unroll")                                                         \
                for (int nt = 0; nt < 8; nt++) {                                          \
                    mma_f16(acc[0][nt], a[0], bb[nt]);                                    \
                    mma_f16(acc[1][nt], a[1], bb[nt]);                                    \
                }                                                                         \
            }                                                                             \
            if (tid == 0 && c + NSTAGE < CH) {                                            \
                mbar_wait(ctrl + stage * 16 + 8, phase);                                  \
                const int cn = c + NSTAGE;                                                \
                MBAR_EXPECT(ctrl + stage * 16, 2 * TILE_B);                               \
                tma2d(tiles + stage * STAGE_B,          tmAp, cn * KC, (mrow0), ctrl + stage * 16); \
                tma2d(tiles + stage * STAGE_B + TILE_B, tmBp, cn * KC, (nrow0), ctrl + stage * 16); \
            }                                                                             \
            if (++stage == NSTAGE) { stage = 0; phase ^= 1; }                             \
        }                                                                                 \
    }                                                                                     \
    __syncthreads();

#define FRAG_ADDR_SETUP()                                                \
    const uint32_t xc = (lane & 7) << 4;                                 \
    const uint32_t qc = (lane >> 4) << 4;                                \
    uint32_t aoff[2], boff[4];                                           \
    _Pragma("unroll")                                                    \
    for (int mt = 0; mt < 2; mt++)                                       \
        aoff[mt] = (wm * 32 + mt * 16 + (lane & 15)) * 128;              \
    _Pragma("unroll")                                                    \
    for (int nt2 = 0; nt2 < 4; nt2++)                                    \
        boff[nt2] = (wn * 64 + nt2 * 16 + (lane & 15)) * 128;

// ---------------- merged QKV projection (z selects q/k/v) ----------------
#define GEMM_PROLOGUE_HOOK
__global__ __launch_bounds__(256, 2)
void proj_qkv(const __grid_constant__ CUtensorMap tmX,
              const __grid_constant__ CUtensorMap tmWq,
              const __grid_constant__ CUtensorMap tmWk,
              const __grid_constant__ CUtensorMap tmWv,
              const float* __restrict__ bq, const float* __restrict__ bk, const float* __restrict__ bv,
              __half* __restrict__ Q, __half* __restrict__ Kmat, __half* __restrict__ VT)
{
    extern __shared__ char smem[];
    const uint32_t sbase = smem_u32(smem);
    const uint32_t tiles = (sbase + 1023) & ~1023u;
    const uint32_t ctrl  = tiles + NSTAGE * STAGE_B;

    const int tid = threadIdx.x, lane = tid & 31, wid = tid >> 5;
    const int wm = wid & 3, wn = wid >> 2;
    const int z = blockIdx.z;
    const int m0 = blockIdx.y * 128, n0 = blockIdx.x * 128;

    const CUtensorMap* tb = (z == 0) ? &tmWq : (z == 1) ? &tmWk : &tmWv;
    const float* bias = (z == 0) ? bq : (z == 1) ? bk : bv;

    FRAG_ADDR_SETUP()

    float acc[2][8][4] = {};
    const int CH = DMODEL / KC;

    GEMM_MAINLOOP(&tmX, tb, m0, n0)

    if (z == 2) {
        float* stg = (float*)smem;
        #pragma unroll
        for (int mt = 0; mt < 2; mt++)
            #pragma unroll
            for (int h = 0; h < 2; h++) {
                int m = wm * 32 + mt * 16 + (lane >> 2) + h * 8;
                #pragma unroll
                for (int nt = 0; nt < 8; nt++) {
                    int n = wn * 64 + nt * 8 + ((lane & 3) << 1);
                    stg[m * 133 + n]     = acc[mt][nt][h * 2 + 0] + __ldg(bias + n0 + n);
                    stg[m * 133 + n + 1] = acc[mt][nt][h * 2 + 1] + __ldg(bias + n0 + n + 1);
                }
            }
        __syncthreads();
        #pragma unroll 4
        for (int i = 0; i < 64; i++) {
            int linear = i * 256 + tid;
            int n = linear >> 7, m = linear & 127;
            float v = stg[m * 133 + n];
            int gm = m0 + m;
            long long idx = ((long long)(gm >> 11) * DMODEL + (n0 + n)) * SEQ + (gm & (SEQ - 1));
            VT[idx] = __float2half_rn(v);
        }
    } else {
        __half* C = (z == 0) ? Q : Kmat;
        #pragma unroll
        for (int mt = 0; mt < 2; mt++)
            #pragma unroll
            for (int h = 0; h < 2; h++) {
                int m = m0 + wm * 32 + mt * 16 + (lane >> 2) + h * 8;
                #pragma unroll
                for (int nt = 0; nt < 8; nt++) {
                    int n = n0 + wn * 64 + nt * 8 + ((lane & 3) << 1);
                    float v0 = acc[mt][nt][h * 2 + 0] + __ldg(bias + n);
                    float v1 = acc[mt][nt][h * 2 + 1] + __ldg(bias + n + 1);
                    __half2 hv = __floats2half2_rn(v0, v1);
                    *(__half2*)(C + (long long)m * DMODEL + n) = hv;
                }
            }
    }
}
#undef GEMM_PROLOGUE_HOOK

// ---------------- scores GEMM (batched z): P16 = fp16(exp(acc/32)) + partials ----------------
#define GEMM_PROLOGUE_HOOK
__global__ __launch_bounds__(256, 2)
void gemm_scores(const __grid_constant__ CUtensorMap tmQ,
                 const __grid_constant__ CUtensorMap tmK,
                 __half* __restrict__ P16, float* __restrict__ partials,
                 float scale)
{
    extern __shared__ char smem[];
    const uint32_t sbase = smem_u32(smem);
    const uint32_t tiles = (sbase + 1023) & ~1023u;
    const uint32_t ctrl  = tiles + NSTAGE * STAGE_B;

    const int tid = threadIdx.x, lane = tid & 31, wid = tid >> 5;
    const int wm = wid & 3, wn = wid >> 2;
    const int z = blockIdx.z;
    const int m0 = blockIdx.y * 128, n0 = blockIdx.x * 128;
    const int mrow0 = m0 + z * SEQ;
    const int nrow0 = n0 + z * SEQ;

    FRAG_ADDR_SETUP()

    float acc[2][8][4] = {};
    const int CH = DMODEL / KC;

    GEMM_MAINLOOP(&tmQ, &tmK, mrow0, nrow0)

    __half* Pz = P16 + (long long)z * SEQ * SEQ;
    #pragma unroll
    for (int mt = 0; mt < 2; mt++)
        #pragma unroll
        for (int h = 0; h < 2; h++) {
            int m = m0 + wm * 32 + mt * 16 + (lane >> 2) + h * 8;
            float rsum = 0.0f;
            #pragma unroll
            for (int nt = 0; nt < 8; nt++) {
                int n = n0 + wn * 64 + nt * 8 + ((lane & 3) << 1);
                float e0 = __expf(acc[mt][nt][h * 2 + 0] * scale);
                float e1 = __expf(acc[mt][nt][h * 2 + 1] * scale);
                rsum += e0 + e1;
                __half2 hv = __floats2half2_rn(e0, e1);
                *(__half2*)(Pz + (long long)m * SEQ + n) = hv;
            }
            rsum += __shfl_xor_sync(0xffffffffu, rsum, 1);
            rsum += __shfl_xor_sync(0xffffffffu, rsum, 2);
            if ((lane & 3) == 0)
                partials[((long long)z * SEQ + m) * 32 + blockIdx.x * 2 + wn] = rsum;
        }
}
#undef GEMM_PROLOGUE_HOOK

// ---------------- PV GEMM (batched z): out = (P V)/rowsum; rowinv fused in prologue ----------------
#define GEMM_PROLOGUE_HOOK                                                 \
    {                                                                      \
        float* sinv = (float*)(smem + (ctrl - sbase) + 128);               \
        if (tid < 128) {                                                   \
            const float4* pp = (const float4*)(partials +                  \
                ((long long)z * SEQ + m0 + tid) * 32);                     \
            float ssum = 0.0f;                                             \
            _Pragma("unroll")                                              \
            for (int i = 0; i < 8; i++) {                                  \
                float4 v = pp[i];                                          \
                ssum += (v.x + v.y) + (v.z + v.w);                         \
            }                                                              \
            sinv[tid] = 1.0f / ssum;                                       \
        }                                                                  \
    }
__global__ __launch_bounds__(256, 2)
void gemm_pv(const __grid_constant__ CUtensorMap tmP,
             const __grid_constant__ CUtensorMap tmVT,
             const float* __restrict__ partials, float* __restrict__ C)
{
    extern __shared__ char smem[];
    const uint32_t sbase = smem_u32(smem);
    const uint32_t tiles = (sbase + 1023) & ~1023u;
    const uint32_t ctrl  = tiles + NSTAGE * STAGE_B;

    const int tid = threadIdx.x, lane = tid & 31, wid = tid >> 5;
    const int wm = wid & 3, wn = wid >> 2;
    const int z = blockIdx.z;
    const int m0 = blockIdx.y * 128, n0 = blockIdx.x * 128;
    const int mrow0 = m0 + z * SEQ;
    const int nrow0 = n0 + z * DMODEL;

    FRAG_ADDR_SETUP()

    float acc[2][8][4] = {};
    const int CH = SEQ / KC;

    GEMM_MAINLOOP(&tmP, &tmVT, mrow0, nrow0)

    const float* sinv = (const float*)(smem + (ctrl - sbase) + 128);
    float* Cz = C + (long long)z * SEQ * DMODEL;
    #pragma unroll
    for (int mt = 0; mt < 2; mt++)
        #pragma unroll
        for (int h = 0; h < 2; h++) {
            int mloc = wm * 32 + mt * 16 + (lane >> 2) + h * 8;
            int m = m0 + mloc;
            float iv = sinv[mloc];
            #pragma unroll
            for (int nt = 0; nt < 8; nt++) {
                int n = n0 + wn * 64 + nt * 8 + ((lane & 3) << 1);
                stg2_cs(Cz + (long long)m * DMODEL + n,
                        acc[mt][nt][h * 2 + 0] * iv,
                        acc[mt][nt][h * 2 + 1] * iv);
            }
        }
}
#undef GEMM_PROLOGUE_HOOK

// ---------------- host: tensormap encode via driver entry point ----------------
typedef CUresult (*EncodeFn)(CUtensorMap*, CUtensorMapDataType, cuuint32_t, void*,
                             const cuuint64_t*, const cuuint64_t*, const cuuint32_t*,
                             const cuuint32_t*, CUtensorMapInterleave, CUtensorMapSwizzle,
                             CUtensorMapL2promotion, CUtensorMapFloatOOBfill);

static void make2d_h(EncodeFn enc, CUtensorMap* m, void* p, unsigned long long rows, unsigned long long cols) {
    cuuint64_t dims[2]    = {cols, rows};
    cuuint64_t strides[1] = {cols * 2};
    cuuint32_t box[2]     = {64, 128};
    cuuint32_t es[2]      = {1, 1};
    enc(m, CU_TENSOR_MAP_DATA_TYPE_FLOAT16, 2, p, dims, strides, box, es,
        CU_TENSOR_MAP_INTERLEAVE_NONE, CU_TENSOR_MAP_SWIZZLE_128B,
        CU_TENSOR_MAP_L2_PROMOTION_L2_128B, CU_TENSOR_MAP_FLOAT_OOB_FILL_NONE);
}

// ---------------- launch ----------------
extern "C" void kernel_launch(void* const* d_in, const int* in_sizes, int n_in,
                              void* d_out, int out_size)
{
    const float* x  = (const float*)d_in[0];
    const float* Wq = (const float*)d_in[1];
    const float* bq = (const float*)d_in[2];
    const float* Wk = (const float*)d_in[3];
    const float* bk = (const float*)d_in[4];
    const float* Wv = (const float*)d_in[5];
    const float* bv = (const float*)d_in[6];
    float* out = (float*)d_out;

    void *xh, *wqt, *wkt, *wvt, *q, *k, *vt, *p, *part;
    cudaGetSymbolAddress(&xh, g_xh);
    cudaGetSymbolAddress(&wqt, g_wqt); cudaGetSymbolAddress(&wkt, g_wkt); cudaGetSymbolAddress(&wvt, g_wvt);
    cudaGetSymbolAddress(&q, g_q); cudaGetSymbolAddress(&k, g_k);
    cudaGetSymbolAddress(&vt, g_vt);
    cudaGetSymbolAddress(&p, g_p);
    cudaGetSymbolAddress(&part, g_part);

    EncodeFn enc = nullptr;
    {
        void* fp = nullptr;
        cudaDriverEntryPointQueryResult qr;
        cudaGetDriverEntryPointByVersion("cuTensorMapEncodeTiled", &fp, 12000,
                                         cudaEnableDefault, &qr);
        enc = (EncodeFn)fp;
    }
    CUtensorMap tm_x, tm_wq, tm_wk, tm_wv, tm_q, tm_k, tm_p, tm_vt;
    make2d_h(enc, &tm_x,  xh,  8192, 1024);
    make2d_h(enc, &tm_wq, wqt, 1024, 1024);
    make2d_h(enc, &tm_wk, wkt, 1024, 1024);
    make2d_h(enc, &tm_wv, wvt, 1024, 1024);
    make2d_h(enc, &tm_q,  q,   8192, 1024);
    make2d_h(enc, &tm_k,  k,   8192, 1024);
    make2d_h(enc, &tm_p,  p,   8192, 2048);
    make2d_h(enc, &tm_vt, vt,  4096, 2048);

    cudaFuncSetAttribute(proj_qkv,    cudaFuncAttributeMaxDynamicSharedMemorySize, DSMEM);
    cudaFuncSetAttribute(gemm_scores, cudaFuncAttributeMaxDynamicSharedMemorySize, DSMEM);
    cudaFuncSetAttribute(gemm_pv,     cudaFuncAttributeMaxDynamicSharedMemorySize, DSMEM);

    const int MQ = BATCH * SEQ; // 8192

    // launch 0: convert x -> fp16
    cvt_kernel<<<MQ * DMODEL / 4 / 256, 256>>>((const float4*)x, (uint2*)xh, MQ * DMODEL / 4);

    // launch 1: transpose + convert all weights
    dim3 gw(DMODEL / 32, DMODEL / 32, 3);
    wtrans3_kernel<<<gw, 256>>>(Wq, Wk, Wv, (__half*)wqt, (__half*)wkt, (__half*)wvt);

    // launch 2: merged QKV projections (z = q/k/v)
    dim3 gp(DMODEL / 128, MQ / 128, 3);
    proj_qkv<<<gp, 256, DSMEM>>>(tm_x, tm_wq, tm_wk, tm_wv, bq, bk, bv,
                                 (__half*)q, (__half*)k, (__half*)vt);

    // launch 3: P = exp(Q K^T / 32) fp16 + row partial sums (batched over z)
    dim3 gs(SEQ / 128, SEQ / 128, BATCH);
    gemm_scores<<<gs, 256, DSMEM>>>(tm_q, tm_k, (__half*)p, (float*)part, 0.03125f);

    // launch 4: out = (P V) * inv[row], rowinv fused into prologue (batched over z)
    dim3 go(DMODEL / 128, SEQ / 128, BATCH);
    gemm_pv<<<go, 256, DSMEM>>>(tm_p, tm_vt, (const float*)part, out);
}